// round 14
// baseline (speedup 1.0000x reference)
#include <cuda_runtime.h>
#include <cuda_fp16.h>
#include <cstdint>

// Problem constants
#define T_LEN   1024
#define BSZ     4
#define EMBED   1024
#define NHEADS  16
#define HDIM    64
#define NBH     (BSZ * NHEADS)      // 64
#define MROWS   (T_LEN * BSZ)       // 4096
#define SCALING 0.125f
#define LOG2E   1.4426950408889634f

// fp16 scratch (hi only); q carries SCALING*LOG2E
__device__ __half g_qh[NBH * T_LEN * HDIM];
__device__ __half g_kh[NBH * T_LEN * HDIM];
__device__ __half g_vh[NBH * T_LEN * HDIM];
__device__ __half g_attnh[MROWS * EMBED];
// fp16 GEMM operands (hi only)
__device__ __half g_Ah[MROWS * EMBED];
__device__ __half g_Bh[3 * EMBED * EMBED];
// mask + key-padding folded, per batch: (B, T, S)
__device__ float g_maskb[BSZ * T_LEN * T_LEN];   // 16 MB

// ---------------------------------------------------------------------------
// PTX helpers
// ---------------------------------------------------------------------------
__device__ __forceinline__ uint32_t s2u(const void* p) {
    return (uint32_t)__cvta_generic_to_shared(p);
}
__device__ __forceinline__ void cp_async16(uint32_t dst, const void* src) {
    asm volatile("cp.async.cg.shared.global [%0], [%1], 16;\n" :: "r"(dst), "l"(src));
}
__device__ __forceinline__ void cp_commit() {
    asm volatile("cp.async.commit_group;\n");
}
template<int N>
__device__ __forceinline__ void cp_wait() {
    asm volatile("cp.async.wait_group %0;\n" :: "n"(N));
}
__device__ __forceinline__ void ldm_x4(uint32_t* r, uint32_t addr) {
    asm volatile("ldmatrix.sync.aligned.m8n8.x4.shared.b16 {%0,%1,%2,%3}, [%4];"
                 : "=r"(r[0]), "=r"(r[1]), "=r"(r[2]), "=r"(r[3]) : "r"(addr));
}
__device__ __forceinline__ void ldm_x4_trans(uint32_t* r, uint32_t addr) {
    asm volatile("ldmatrix.sync.aligned.m8n8.x4.trans.shared.b16 {%0,%1,%2,%3}, [%4];"
                 : "=r"(r[0]), "=r"(r[1]), "=r"(r[2]), "=r"(r[3]) : "r"(addr));
}
__device__ __forceinline__ void mma16816(float* c, const uint32_t* a, const uint32_t* b) {
    asm volatile("mma.sync.aligned.m16n8k16.row.col.f32.f16.f16.f32 "
                 "{%0,%1,%2,%3}, {%4,%5,%6,%7}, {%8,%9}, {%0,%1,%2,%3};"
                 : "+f"(c[0]), "+f"(c[1]), "+f"(c[2]), "+f"(c[3])
                 : "r"(a[0]), "r"(a[1]), "r"(a[2]), "r"(a[3]), "r"(b[0]), "r"(b[1]));
}
__device__ __forceinline__ float ex2f(float x) {
    float y;
    asm("ex2.approx.ftz.f32 %0, %1;" : "=f"(y) : "f"(x));
    return y;
}
__device__ __host__ __forceinline__ uint32_t sw128(uint32_t off) {
    return off ^ ((off >> 3) & 0x70);
}
__device__ __forceinline__ uint32_t pack_hi2(float a, float b) {
    __half2 t; t.x = __float2half_rn(a); t.y = __float2half_rn(b);
    uint32_t r; memcpy(&r, &t, 4); return r;
}

// ---------------------------------------------------------------------------
// Prep kernels
// ---------------------------------------------------------------------------
__global__ __launch_bounds__(256)
void split_hi_kernel(const float* __restrict__ src, __half* __restrict__ hi, int n4)
{
    int i = blockIdx.x * 256 + threadIdx.x;
    if (i >= n4) return;
    float4 v = reinterpret_cast<const float4*>(src)[i];
    reinterpret_cast<uint32_t*>(hi)[2 * i]     = pack_hi2(v.x, v.y);
    reinterpret_cast<uint32_t*>(hi)[2 * i + 1] = pack_hi2(v.z, v.w);
}

// mask_b[b][t][s] = mask[t][s] + (kpm[b][s] ? -1e30 : 0)
__global__ __launch_bounds__(256)
void prep_mask_kernel(const float* __restrict__ mask, const int* __restrict__ kpm)
{
    int i = blockIdx.x * 256 + threadIdx.x;        // over BSZ*T*T/4
    int idx = i * 4;
    int b = idx >> 20;
    int rem = idx & ((1 << 20) - 1);
    int t = rem >> 10;
    int s = rem & 1023;
    float4 m = *reinterpret_cast<const float4*>(mask + (size_t)t * T_LEN + s);
    const int* kp = kpm + b * T_LEN + s;
    float4 o;
    o.x = m.x + (kp[0] ? -1e30f : 0.f);
    o.y = m.y + (kp[1] ? -1e30f : 0.f);
    o.z = m.z + (kp[2] ? -1e30f : 0.f);
    o.w = m.w + (kp[3] ? -1e30f : 0.f);
    reinterpret_cast<float4*>(g_maskb)[i] = o;
}

// ---------------------------------------------------------------------------
// mma.sync fp16 single-product GEMM: D = Ah*Bh. 3-stage pipeline, 2 CTAs/SM.
// ---------------------------------------------------------------------------
#define GK 1024
#define TM 128
#define TN 128
#define TBK 32
#define NKS (GK / TBK)
#define A_ST 40
#define TILE_B (128 * A_ST * 2)     // 10240
#define STAGE_B (2 * TILE_B)        // Ah, Bh = 20480
#define GEMM_SMEM (3 * STAGE_B)     // 61440

__device__ __forceinline__ void load_stage(uint32_t sbase,
    const __half* __restrict__ Ah, const __half* __restrict__ Bh,
    int row0, int col0, int k0, int tid)
{
#pragma unroll
    for (int it = 0; it < 2; it++) {
        int idx = it * 256 + tid;
        int r = idx >> 2, c = idx & 3;
        uint32_t so = r * (A_ST * 2) + c * 16;
        size_t ga = (size_t)(row0 + r) * GK + k0 + c * 8;
        size_t gb = (size_t)(col0 + r) * GK + k0 + c * 8;
        cp_async16(sbase + 0 * TILE_B + so, Ah + ga);
        cp_async16(sbase + 1 * TILE_B + so, Bh + gb);
    }
}

__global__ __launch_bounds__(256, 2)
void gemm_mma(const __half* __restrict__ Ah, const __half* __restrict__ Bh,
              const float* __restrict__ bias, int mode, float* __restrict__ out)
{
    extern __shared__ char smc[];
    const uint32_t sb = s2u(smc);
    const int tid  = threadIdx.x;
    const int lane = tid & 31;
    const int wid  = tid >> 5;
    const int wr = wid & 1;
    const int wc = wid >> 1;
    const int row0 = blockIdx.y * TM, col0 = blockIdx.x * TN;

    const int a_row = lane & 15;
    const int a_k8  = (lane >> 4) * 8;
    const int b_mat = lane >> 3;
    const int b_nf_off = b_mat >> 1;
    const int b_k8  = (b_mat & 1) * 8;
    const int b_row = lane & 7;

    float acc[4][4][4];
#pragma unroll
    for (int i = 0; i < 4; i++)
#pragma unroll
        for (int j = 0; j < 4; j++)
#pragma unroll
            for (int q = 0; q < 4; q++) acc[i][j][q] = 0.f;

    load_stage(sb, Ah, Bh, row0, col0, 0, tid);
    cp_commit();
    load_stage(sb + STAGE_B, Ah, Bh, row0, col0, TBK, tid);
    cp_commit();

    int cur = 0;
    for (int ks = 0; ks < NKS; ks++) {
        if (ks + 2 < NKS) {
            int nxt2 = cur + 2; if (nxt2 >= 3) nxt2 -= 3;
            load_stage(sb + (uint32_t)nxt2 * STAGE_B,
                       Ah, Bh, row0, col0, (ks + 2) * TBK, tid);
            cp_commit();
            cp_wait<2>();
        } else if (ks + 1 < NKS) {
            cp_wait<1>();
        } else {
            cp_wait<0>();
        }
        __syncthreads();
        const uint32_t curb = sb + (uint32_t)cur * STAGE_B;

#pragma unroll
        for (int kk = 0; kk < 2; kk++) {
            const int k0 = kk * 16;
            uint32_t afh[4][4];
#pragma unroll
            for (int mf = 0; mf < 4; mf++) {
                uint32_t aoff = (uint32_t)((wr * 64 + mf * 16 + a_row) * A_ST + k0 + a_k8) * 2;
                ldm_x4(afh[mf], curb + 0 * TILE_B + aoff);
            }
            uint32_t bfh[2][4];
#pragma unroll
            for (int nfp = 0; nfp < 2; nfp++) {
                uint32_t boff = (uint32_t)((wc * 32 + (2 * nfp + b_nf_off) * 8 + b_row) * A_ST
                                           + k0 + b_k8) * 2;
                ldm_x4(bfh[nfp], curb + 1 * TILE_B + boff);
            }
#pragma unroll
            for (int mf = 0; mf < 4; mf++)
#pragma unroll
                for (int nfp = 0; nfp < 2; nfp++)
#pragma unroll
                    for (int half = 0; half < 2; half++) {
                        const int nf = 2 * nfp + half;
                        mma16816(acc[mf][nf], afh[mf], bfh[nfp] + half * 2);
                    }
        }
        __syncthreads();
        cur++; if (cur >= 3) cur -= 3;
    }

    const int g = lane >> 2, tig = lane & 3;
#pragma unroll
    for (int nf = 0; nf < 4; nf++) {
        const int e = col0 + wc * 32 + nf * 8 + tig * 2;
        const float bz0 = __ldg(bias + e);
        const float bz1 = __ldg(bias + e + 1);
#pragma unroll
        for (int mf = 0; mf < 4; mf++) {
#pragma unroll
            for (int half = 0; half < 2; half++) {
                const int m = row0 + wr * 64 + mf * 16 + g + half * 8;
                float v0 = acc[mf][nf][half * 2 + 0] + bz0;
                float v1 = acc[mf][nf][half * 2 + 1] + bz1;
                if (mode == 0) {
                    const int t = m >> 2, b = m & 3;
                    const int which = e >> 10;
                    const int rem = e & 1023;
                    const int h = rem >> 6, d = rem & 63;
                    const int n = (b << 4) + h;
                    size_t off = ((size_t)n << 16) + ((size_t)t << 6) + d;
                    if (which == 0) {
                        const float qs = SCALING * LOG2E;   // exp2-form softmax
                        v0 *= qs; v1 *= qs;
                    }
                    __half* dh = (which == 0) ? g_qh : (which == 1) ? g_kh : g_vh;
                    *reinterpret_cast<uint32_t*>(dh + off) = pack_hi2(v0, v1);
                } else {
                    *reinterpret_cast<float2*>(out + (size_t)m * EMBED + e)
                        = make_float2(v0, v1);
                }
            }
        }
    }
}

// ---------------------------------------------------------------------------
// Flash attention — exp2 softmax, mask_b folded, fp16 single-product.
// 3-stage KV+bias pipeline.
// ---------------------------------------------------------------------------
#define ABT 128
#define ABS 64
#define NBLK (T_LEN / ABS)   // 16
#define AQ_H   0
#define AST0   16384
#define S_KH    0
#define S_VH    8192
#define S_BIAS  16384
#define BIAS_ST 68
#define AST_STRIDE (16384 + 128 * BIAS_ST * 4)   // 51200
#define ATTN_SMEM (AST0 + 3 * AST_STRIDE)        // 169984

__global__ __launch_bounds__(256, 1)
void attn_mma_kernel(const float* __restrict__ attn_bias)
{
    extern __shared__ char smc[];
    const uint32_t sb = s2u(smc);
    const int tid = threadIdx.x, lane = tid & 31, wid = tid >> 5;
    const int n = blockIdx.y, t0 = blockIdx.x * ABT;
    const int b = n >> 4, h = n & 15;
    const int wr0 = wid * 16;
    const int g = lane >> 2, qr = lane & 3;
    const size_t nbase = (size_t)n << 16;
    const float* biasg = attn_bias + (size_t)n * T_LEN * T_LEN;
    const float* maskb = g_maskb + (size_t)b * T_LEN * T_LEN;

    auto load_kv_stage = [&](int blk) {
        const int s0 = blk * ABS;
        const uint32_t B = sb + AST0 + (uint32_t)(blk % 3) * AST_STRIDE;
#pragma unroll
        for (int it = 0; it < 2; it++) {
            int idx = it * 256 + tid;
            int row = idx >> 3, c = idx & 7;
            uint32_t so = sw128(row * 128 + c * 16);
            size_t go = nbase + (size_t)(s0 + row) * 64 + c * 8;
            cp_async16(B + S_KH + so, g_kh + go);
            cp_async16(B + S_VH + so, g_vh + go);
        }
#pragma unroll
        for (int it = 0; it < 8; it++) {
            int idx = it * 256 + tid;
            int row = idx >> 4, c = idx & 15;
            cp_async16(B + S_BIAS + row * (BIAS_ST * 4) + c * 16,
                       biasg + (size_t)(t0 + row) * T_LEN + s0 + c * 4);
        }
    };

    // --- prologue: Q(hi, pre-scaled by 0.125*log2e) + stages 0,1 ---
    {
        const __half* Qh = g_qh + nbase + (size_t)t0 * 64;
#pragma unroll
        for (int it = 0; it < 4; it++) {
            int idx = it * 256 + tid;
            int row = idx >> 3, c = idx & 7;
            uint32_t so = sw128(row * 128 + c * 16);
            cp_async16(sb + AQ_H + so, Qh + row * 64 + c * 8);
        }
        load_kv_stage(0);
        cp_commit();
        load_kv_stage(1);
        cp_commit();
    }

    float m0 = -1e30f, m1 = -1e30f, l0 = 0.f, l1 = 0.f;
    float O[8][4];
#pragma unroll
    for (int i = 0; i < 8; i++)
#pragma unroll
        for (int q = 0; q < 4; q++) O[i][q] = 0.f;
    uint32_t qfh[4][4];

    const int tr0 = t0 + wr0 + g, tr1 = tr0 + 8;
    const int tl0 = wr0 + g;

    const int k_mat = lane >> 3;
    const int k_nf_off = k_mat >> 1;
    const int k_k8 = (k_mat & 1) * 8;
    const int k_row = lane & 7;
    const int v_blk = lane >> 4;
    const int v_row = lane & 15;

    int cur = 0;
    for (int blk = 0; blk < NBLK; blk++) {
        // mask_b prefetch to regs (kpm already folded in)
        float2 mk0[8], mk1[8];
        {
            const int s0g = blk * ABS;
#pragma unroll
            for (int nf = 0; nf < 8; nf++) {
                const int scol = s0g + nf * 8 + qr * 2;
                mk0[nf] = __ldg(reinterpret_cast<const float2*>(maskb + (size_t)tr0 * T_LEN + scol));
                mk1[nf] = __ldg(reinterpret_cast<const float2*>(maskb + (size_t)tr1 * T_LEN + scol));
            }
        }
        if (blk + 2 < NBLK) {
            load_kv_stage(blk + 2);
            cp_commit();
            cp_wait<2>();
        } else if (blk + 1 < NBLK) {
            cp_wait<1>();
        } else {
            cp_wait<0>();
        }
        __syncthreads();

        if (blk == 0) {
#pragma unroll
            for (int ks = 0; ks < 4; ks++) {
                uint32_t aoff = sw128((uint32_t)(wr0 + (lane & 15)) * 128 +
                                      (uint32_t)(ks * 16 + (lane >> 4) * 8) * 2);
                ldm_x4(qfh[ks], sb + AQ_H + aoff);
            }
        }

        const uint32_t B = sb + AST0 + (uint32_t)cur * AST_STRIDE;

        // ---- S2 = (Q*log2e) K ----
        float S[8][4];
#pragma unroll
        for (int i = 0; i < 8; i++)
#pragma unroll
            for (int q = 0; q < 4; q++) S[i][q] = 0.f;
#pragma unroll
        for (int ks = 0; ks < 4; ks++) {
#pragma unroll
            for (int nfp = 0; nfp < 4; nfp++) {
                uint32_t boff = sw128((uint32_t)((2 * nfp + k_nf_off) * 8 + k_row) * 128 +
                                      (uint32_t)(ks * 16 + k_k8) * 2);
                uint32_t kh[4];
                ldm_x4(kh, B + S_KH + boff);
                mma16816(S[2 * nfp + 0], qfh[ks], kh);
                mma16816(S[2 * nfp + 1], qfh[ks], kh + 2);
            }
        }

        // ---- S2 += (mask_b + bias)*log2e ; row max ----
        const float* bias_s = (const float*)(smc + AST0 + (size_t)cur * AST_STRIDE + S_BIAS);
        float rmax0 = -1e30f, rmax1 = -1e30f;
#pragma unroll
        for (int nf = 0; nf < 8; nf++) {
            const int sloc = nf * 8 + qr * 2;
            float2 ba = *reinterpret_cast<const float2*>(bias_s + (size_t)tl0 * BIAS_ST + sloc);
            float2 bb = *reinterpret_cast<const float2*>(bias_s + (size_t)(tl0 + 8) * BIAS_ST + sloc);
            S[nf][0] = fmaf(mk0[nf].x + ba.x, LOG2E, S[nf][0]);
            S[nf][1] = fmaf(mk0[nf].y + ba.y, LOG2E, S[nf][1]);
            S[nf][2] = fmaf(mk1[nf].x + bb.x, LOG2E, S[nf][2]);
            S[nf][3] = fmaf(mk1[nf].y + bb.y, LOG2E, S[nf][3]);
            rmax0 = fmaxf(rmax0, fmaxf(S[nf][0], S[nf][1]));
            rmax1 = fmaxf(rmax1, fmaxf(S[nf][2], S[nf][3]));
        }
        rmax0 = fmaxf(rmax0, __shfl_xor_sync(0xffffffffu, rmax0, 1));
        rmax0 = fmaxf(rmax0, __shfl_xor_sync(0xffffffffu, rmax0, 2));
        rmax1 = fmaxf(rmax1, __shfl_xor_sync(0xffffffffu, rmax1, 1));
        rmax1 = fmaxf(rmax1, __shfl_xor_sync(0xffffffffu, rmax1, 2));

        const float mn0 = fmaxf(m0, rmax0), mn1 = fmaxf(m1, rmax1);
        const float es0 = ex2f(m0 - mn0), es1 = ex2f(m1 - mn1);
        m0 = mn0; m1 = mn1;

        float rs0 = 0.f, rs1 = 0.f;
#pragma unroll
        for (int nf = 0; nf < 8; nf++) {
            S[nf][0] = ex2f(S[nf][0] - mn0);
            S[nf][1] = ex2f(S[nf][1] - mn0);
            S[nf][2] = ex2f(S[nf][2] - mn1);
            S[nf][3] = ex2f(S[nf][3] - mn1);
            rs0 += S[nf][0] + S[nf][1];
            rs1 += S[nf][2] + S[nf][3];
        }
        rs0 += __shfl_xor_sync(0xffffffffu, rs0, 1);
        rs0 += __shfl_xor_sync(0xffffffffu, rs0, 2);
        rs1 += __shfl_xor_sync(0xffffffffu, rs1, 1);
        rs1 += __shfl_xor_sync(0xffffffffu, rs1, 2);
        l0 = l0 * es0 + rs0;
        l1 = l1 * es1 + rs1;

#pragma unroll
        for (int i = 0; i < 8; i++) {
            O[i][0] *= es0; O[i][1] *= es0;
            O[i][2] *= es1; O[i][3] *= es1;
        }

        // ---- O += Ph Vh ----
#pragma unroll
        for (int kp = 0; kp < 4; kp++) {
            uint32_t ah[4];
            ah[0] = pack_hi2(S[2*kp][0],   S[2*kp][1]);
            ah[1] = pack_hi2(S[2*kp][2],   S[2*kp][3]);
            ah[2] = pack_hi2(S[2*kp+1][0], S[2*kp+1][1]);
            ah[3] = pack_hi2(S[2*kp+1][2], S[2*kp+1][3]);
#pragma unroll
            for (int np = 0; np < 4; np++) {
                uint32_t voff = sw128((uint32_t)(kp * 16 + v_row) * 128 +
                                      (uint32_t)(2 * np + v_blk) * 16);
                uint32_t vh[4];
                ldm_x4_trans(vh, B + S_VH + voff);
                mma16816(O[2 * np + 0], ah, vh);
                mma16816(O[2 * np + 1], ah, vh + 2);
            }
        }
        __syncthreads();
        cur++; if (cur >= 3) cur -= 3;
    }

    // ---- normalize + write fp16 hi ----
    const float inv0 = 1.f / l0, inv1 = 1.f / l1;
    const size_t base0 = ((size_t)tr0 * BSZ + b) * EMBED + h * 64;
    const size_t base1 = ((size_t)tr1 * BSZ + b) * EMBED + h * 64;
#pragma unroll
    for (int nf2 = 0; nf2 < 8; nf2++) {
        const int d0 = nf2 * 8 + qr * 2;
        float v0 = O[nf2][0] * inv0, v1 = O[nf2][1] * inv0;
        float w0 = O[nf2][2] * inv1, w1 = O[nf2][3] * inv1;
        *reinterpret_cast<uint32_t*>(g_attnh + base0 + d0) = pack_hi2(v0, v1);
        *reinterpret_cast<uint32_t*>(g_attnh + base1 + d0) = pack_hi2(w0, w1);
    }
}

// ---------------------------------------------------------------------------
extern "C" void kernel_launch(void* const* d_in, const int* in_sizes, int n_in,
                              void* d_out, int out_size)
{
    const float* query     = (const float*)d_in[0];
    const int*   kpm       = (const int*)  d_in[1];
    const float* attn_mask = (const float*)d_in[2];
    const float* attn_bias = (const float*)d_in[3];
    const float* W_in      = (const float*)d_in[4];
    const float* b_in      = (const float*)d_in[5];
    const float* W_out     = (const float*)d_in[6];
    const float* b_out     = (const float*)d_in[7];
    float*       out       = (float*)d_out;

    static bool attr_set = false;
    if (!attr_set) {
        cudaFuncSetAttribute(gemm_mma, cudaFuncAttributeMaxDynamicSharedMemorySize, GEMM_SMEM);
        cudaFuncSetAttribute(attn_mma_kernel, cudaFuncAttributeMaxDynamicSharedMemorySize, ATTN_SMEM);
        attr_set = true;
    }

    __half *Ah, *Bh, *ATh;
    cudaGetSymbolAddress((void**)&Ah, g_Ah);
    cudaGetSymbolAddress((void**)&Bh, g_Bh);
    cudaGetSymbolAddress((void**)&ATh, g_attnh);

    // 1) prep: hi-only splits + mask fold
    split_hi_kernel<<<MROWS * EMBED / 4 / 256, 256>>>(query, Ah, MROWS * EMBED / 4);
    split_hi_kernel<<<3 * EMBED * EMBED / 4 / 256, 256>>>(W_in, Bh, 3 * EMBED * EMBED / 4);
    prep_mask_kernel<<<BSZ * T_LEN * T_LEN / 4 / 256, 256>>>(attn_mask, kpm);

    // 2) QKV projection -> fp16 q(scaled by 0.125*log2e)/k/v
    {
        dim3 grid(3 * EMBED / TN, MROWS / TM);   // (24, 32)
        gemm_mma<<<grid, 256, GEMM_SMEM>>>(Ah, Bh, b_in, 0, nullptr);
    }

    // 3) Flash attention -> fp16 attn (hi)
    {
        dim3 grid(T_LEN / ABT, NBH);   // (8, 64)
        attn_mma_kernel<<<grid, 256, ATTN_SMEM>>>(attn_bias);
    }

    // 4) split W_out (hi); output projection (A = attn fp16 hi)
    split_hi_kernel<<<EMBED * EMBED / 4 / 256, 256>>>(W_out, Bh, EMBED * EMBED / 4);
    {
        dim3 grid(EMBED / TN, MROWS / TM);       // (8, 32)
        gemm_mma<<<grid, 256, GEMM_SMEM>>>(ATh, Bh, b_out, 1, out);
    }
}

// round 17
// speedup vs baseline: 1.0555x; 1.0555x over previous
#include <cuda_runtime.h>
#include <cuda_fp16.h>
#include <cstdint>

// Problem constants
#define T_LEN   1024
#define BSZ     4
#define EMBED   1024
#define NHEADS  16
#define HDIM    64
#define NBH     (BSZ * NHEADS)      // 64
#define MROWS   (T_LEN * BSZ)       // 4096
#define SCALING 0.125f
#define LOG2E   1.4426950408889634f

// fp16 scratch (hi only); q carries SCALING*LOG2E
__device__ __half g_qh[NBH * T_LEN * HDIM];
__device__ __half g_kh[NBH * T_LEN * HDIM];
__device__ __half g_vh[NBH * T_LEN * HDIM];
__device__ __half g_attnh[MROWS * EMBED];
// fp16 GEMM operands (hi only)
__device__ __half g_Ah[MROWS * EMBED];
__device__ __half g_Bh[3 * EMBED * EMBED];
// mask + key-padding folded, per batch: (B, T, S)
__device__ float g_maskb[BSZ * T_LEN * T_LEN];   // 16 MB

// ---------------------------------------------------------------------------
// PTX helpers
// ---------------------------------------------------------------------------
__device__ __forceinline__ uint32_t s2u(const void* p) {
    return (uint32_t)__cvta_generic_to_shared(p);
}
__device__ __forceinline__ void cp_async16(uint32_t dst, const void* src) {
    asm volatile("cp.async.cg.shared.global [%0], [%1], 16;\n" :: "r"(dst), "l"(src));
}
__device__ __forceinline__ void cp_commit() {
    asm volatile("cp.async.commit_group;\n");
}
template<int N>
__device__ __forceinline__ void cp_wait() {
    asm volatile("cp.async.wait_group %0;\n" :: "n"(N));
}
__device__ __forceinline__ void ldm_x4(uint32_t* r, uint32_t addr) {
    asm volatile("ldmatrix.sync.aligned.m8n8.x4.shared.b16 {%0,%1,%2,%3}, [%4];"
                 : "=r"(r[0]), "=r"(r[1]), "=r"(r[2]), "=r"(r[3]) : "r"(addr));
}
__device__ __forceinline__ void ldm_x4_trans(uint32_t* r, uint32_t addr) {
    asm volatile("ldmatrix.sync.aligned.m8n8.x4.trans.shared.b16 {%0,%1,%2,%3}, [%4];"
                 : "=r"(r[0]), "=r"(r[1]), "=r"(r[2]), "=r"(r[3]) : "r"(addr));
}
__device__ __forceinline__ void mma16816(float* c, const uint32_t* a, const uint32_t* b) {
    asm volatile("mma.sync.aligned.m16n8k16.row.col.f32.f16.f16.f32 "
                 "{%0,%1,%2,%3}, {%4,%5,%6,%7}, {%8,%9}, {%0,%1,%2,%3};"
                 : "+f"(c[0]), "+f"(c[1]), "+f"(c[2]), "+f"(c[3])
                 : "r"(a[0]), "r"(a[1]), "r"(a[2]), "r"(a[3]), "r"(b[0]), "r"(b[1]));
}
__device__ __forceinline__ float ex2f(float x) {
    float y;
    asm("ex2.approx.ftz.f32 %0, %1;" : "=f"(y) : "f"(x));
    return y;
}
__device__ __host__ __forceinline__ uint32_t sw128(uint32_t off) {
    return off ^ ((off >> 3) & 0x70);
}
__device__ __forceinline__ uint32_t pack_hi2(float a, float b) {
    __half2 t; t.x = __float2half_rn(a); t.y = __float2half_rn(b);
    uint32_t r; memcpy(&r, &t, 4); return r;
}

// ---------------------------------------------------------------------------
// Prep kernels
// ---------------------------------------------------------------------------
__global__ __launch_bounds__(256)
void split_hi_kernel(const float* __restrict__ src, __half* __restrict__ hi, int n4)
{
    int i = blockIdx.x * 256 + threadIdx.x;
    if (i >= n4) return;
    float4 v = reinterpret_cast<const float4*>(src)[i];
    reinterpret_cast<uint32_t*>(hi)[2 * i]     = pack_hi2(v.x, v.y);
    reinterpret_cast<uint32_t*>(hi)[2 * i + 1] = pack_hi2(v.z, v.w);
}

// mask_b[b][t][s] = mask[t][s] + (kpm[b][s] ? -1e30 : 0)
__global__ __launch_bounds__(256)
void prep_mask_kernel(const float* __restrict__ mask, const int* __restrict__ kpm)
{
    int i = blockIdx.x * 256 + threadIdx.x;        // over BSZ*T*T/4
    int idx = i * 4;
    int b = idx >> 20;
    int rem = idx & ((1 << 20) - 1);
    int t = rem >> 10;
    int s = rem & 1023;
    float4 m = *reinterpret_cast<const float4*>(mask + (size_t)t * T_LEN + s);
    const int* kp = kpm + b * T_LEN + s;
    float4 o;
    o.x = m.x + (kp[0] ? -1e30f : 0.f);
    o.y = m.y + (kp[1] ? -1e30f : 0.f);
    o.z = m.z + (kp[2] ? -1e30f : 0.f);
    o.w = m.w + (kp[3] ? -1e30f : 0.f);
    reinterpret_cast<float4*>(g_maskb)[i] = o;
}

// ---------------------------------------------------------------------------
// mma.sync fp16 single-product GEMM: D = Ah*Bh.
// 3-stage pipeline, ONE barrier per k-iter (load issued after the barrier).
// ---------------------------------------------------------------------------
#define GK 1024
#define TM 128
#define TN 128
#define TBK 32
#define NKS (GK / TBK)
#define A_ST 40
#define TILE_B (128 * A_ST * 2)     // 10240
#define STAGE_B (2 * TILE_B)        // Ah, Bh = 20480
#define GEMM_SMEM (3 * STAGE_B)     // 61440

__device__ __forceinline__ void load_stage(uint32_t sbase,
    const __half* __restrict__ Ah, const __half* __restrict__ Bh,
    int row0, int col0, int k0, int tid)
{
#pragma unroll
    for (int it = 0; it < 2; it++) {
        int idx = it * 256 + tid;
        int r = idx >> 2, c = idx & 3;
        uint32_t so = r * (A_ST * 2) + c * 16;
        size_t ga = (size_t)(row0 + r) * GK + k0 + c * 8;
        size_t gb = (size_t)(col0 + r) * GK + k0 + c * 8;
        cp_async16(sbase + 0 * TILE_B + so, Ah + ga);
        cp_async16(sbase + 1 * TILE_B + so, Bh + gb);
    }
}

__global__ __launch_bounds__(256, 2)
void gemm_mma(const __half* __restrict__ Ah, const __half* __restrict__ Bh,
              const float* __restrict__ bias, int mode, float* __restrict__ out)
{
    extern __shared__ char smc[];
    const uint32_t sb = s2u(smc);
    const int tid  = threadIdx.x;
    const int lane = tid & 31;
    const int wid  = tid >> 5;
    const int wr = wid & 1;
    const int wc = wid >> 1;
    const int row0 = blockIdx.y * TM, col0 = blockIdx.x * TN;

    const int a_row = lane & 15;
    const int a_k8  = (lane >> 4) * 8;
    const int b_mat = lane >> 3;
    const int b_nf_off = b_mat >> 1;
    const int b_k8  = (b_mat & 1) * 8;
    const int b_row = lane & 7;

    float acc[4][4][4];
#pragma unroll
    for (int i = 0; i < 4; i++)
#pragma unroll
        for (int j = 0; j < 4; j++)
#pragma unroll
            for (int q = 0; q < 4; q++) acc[i][j][q] = 0.f;

    load_stage(sb, Ah, Bh, row0, col0, 0, tid);
    cp_commit();
    load_stage(sb + STAGE_B, Ah, Bh, row0, col0, TBK, tid);
    cp_commit();

    int cur = 0;
    for (int ks = 0; ks < NKS; ks++) {
        // wait for stage `cur`, then ONE barrier
        if (ks + 1 < NKS) cp_wait<1>(); else cp_wait<0>();
        __syncthreads();
        // safe to refill stage (cur+2)%3: all warps finished consuming it (iter ks-1)
        if (ks + 2 < NKS) {
            int nxt2 = cur + 2; if (nxt2 >= 3) nxt2 -= 3;
            load_stage(sb + (uint32_t)nxt2 * STAGE_B,
                       Ah, Bh, row0, col0, (ks + 2) * TBK, tid);
            cp_commit();
        }
        const uint32_t curb = sb + (uint32_t)cur * STAGE_B;

#pragma unroll
        for (int kk = 0; kk < 2; kk++) {
            const int k0 = kk * 16;
            uint32_t afh[4][4];
#pragma unroll
            for (int mf = 0; mf < 4; mf++) {
                uint32_t aoff = (uint32_t)((wr * 64 + mf * 16 + a_row) * A_ST + k0 + a_k8) * 2;
                ldm_x4(afh[mf], curb + 0 * TILE_B + aoff);
            }
            uint32_t bfh[2][4];
#pragma unroll
            for (int nfp = 0; nfp < 2; nfp++) {
                uint32_t boff = (uint32_t)((wc * 32 + (2 * nfp + b_nf_off) * 8 + b_row) * A_ST
                                           + k0 + b_k8) * 2;
                ldm_x4(bfh[nfp], curb + 1 * TILE_B + boff);
            }
#pragma unroll
            for (int mf = 0; mf < 4; mf++)
#pragma unroll
                for (int nfp = 0; nfp < 2; nfp++)
#pragma unroll
                    for (int half = 0; half < 2; half++) {
                        const int nf = 2 * nfp + half;
                        mma16816(acc[mf][nf], afh[mf], bfh[nfp] + half * 2);
                    }
        }
        cur++; if (cur >= 3) cur -= 3;
    }

    const int g = lane >> 2, tig = lane & 3;
#pragma unroll
    for (int nf = 0; nf < 4; nf++) {
        const int e = col0 + wc * 32 + nf * 8 + tig * 2;
        const float bz0 = __ldg(bias + e);
        const float bz1 = __ldg(bias + e + 1);
#pragma unroll
        for (int mf = 0; mf < 4; mf++) {
#pragma unroll
            for (int half = 0; half < 2; half++) {
                const int m = row0 + wr * 64 + mf * 16 + g + half * 8;
                float v0 = acc[mf][nf][half * 2 + 0] + bz0;
                float v1 = acc[mf][nf][half * 2 + 1] + bz1;
                if (mode == 0) {
                    const int t = m >> 2, b = m & 3;
                    const int which = e >> 10;
                    const int rem = e & 1023;
                    const int h = rem >> 6, d = rem & 63;
                    const int n = (b << 4) + h;
                    size_t off = ((size_t)n << 16) + ((size_t)t << 6) + d;
                    if (which == 0) {
                        const float qs = SCALING * LOG2E;   // exp2-form softmax
                        v0 *= qs; v1 *= qs;
                    }
                    __half* dh = (which == 0) ? g_qh : (which == 1) ? g_kh : g_vh;
                    *reinterpret_cast<uint32_t*>(dh + off) = pack_hi2(v0, v1);
                } else {
                    *reinterpret_cast<float2*>(out + (size_t)m * EMBED + e)
                        = make_float2(v0, v1);
                }
            }
        }
    }
}

// ---------------------------------------------------------------------------
// Flash attention — exp2 softmax, mask_b folded, fp16 single-product.
// 3-stage KV+bias pipeline, ONE barrier per block-iter.
// ---------------------------------------------------------------------------
#define ABT 128
#define ABS 64
#define NBLK (T_LEN / ABS)   // 16
#define AQ_H   0
#define AST0   16384
#define S_KH    0
#define S_VH    8192
#define S_BIAS  16384
#define BIAS_ST 68
#define AST_STRIDE (16384 + 128 * BIAS_ST * 4)   // 51200
#define ATTN_SMEM (AST0 + 3 * AST_STRIDE)        // 169984

__global__ __launch_bounds__(256, 1)
void attn_mma_kernel(const float* __restrict__ attn_bias)
{
    extern __shared__ char smc[];
    const uint32_t sb = s2u(smc);
    const int tid = threadIdx.x, lane = tid & 31, wid = tid >> 5;
    const int n = blockIdx.y, t0 = blockIdx.x * ABT;
    const int b = n >> 4, h = n & 15;
    const int wr0 = wid * 16;
    const int g = lane >> 2, qr = lane & 3;
    const size_t nbase = (size_t)n << 16;
    const float* biasg = attn_bias + (size_t)n * T_LEN * T_LEN;
    const float* maskb = g_maskb + (size_t)b * T_LEN * T_LEN;

    auto load_kv_stage = [&](int blk) {
        const int s0 = blk * ABS;
        const uint32_t B = sb + AST0 + (uint32_t)(blk % 3) * AST_STRIDE;
#pragma unroll
        for (int it = 0; it < 2; it++) {
            int idx = it * 256 + tid;
            int row = idx >> 3, c = idx & 7;
            uint32_t so = sw128(row * 128 + c * 16);
            size_t go = nbase + (size_t)(s0 + row) * 64 + c * 8;
            cp_async16(B + S_KH + so, g_kh + go);
            cp_async16(B + S_VH + so, g_vh + go);
        }
#pragma unroll
        for (int it = 0; it < 8; it++) {
            int idx = it * 256 + tid;
            int row = idx >> 4, c = idx & 15;
            cp_async16(B + S_BIAS + row * (BIAS_ST * 4) + c * 16,
                       biasg + (size_t)(t0 + row) * T_LEN + s0 + c * 4);
        }
    };

    // --- prologue: Q(hi, pre-scaled) + stages 0,1 ---
    {
        const __half* Qh = g_qh + nbase + (size_t)t0 * 64;
#pragma unroll
        for (int it = 0; it < 4; it++) {
            int idx = it * 256 + tid;
            int row = idx >> 3, c = idx & 7;
            uint32_t so = sw128(row * 128 + c * 16);
            cp_async16(sb + AQ_H + so, Qh + row * 64 + c * 8);
        }
        load_kv_stage(0);
        cp_commit();
        load_kv_stage(1);
        cp_commit();
    }

    float m0 = -1e30f, m1 = -1e30f, l0 = 0.f, l1 = 0.f;
    float O[8][4];
#pragma unroll
    for (int i = 0; i < 8; i++)
#pragma unroll
        for (int q = 0; q < 4; q++) O[i][q] = 0.f;
    uint32_t qfh[4][4];

    const int tr0 = t0 + wr0 + g, tr1 = tr0 + 8;
    const int tl0 = wr0 + g;

    const int k_mat = lane >> 3;
    const int k_nf_off = k_mat >> 1;
    const int k_k8 = (k_mat & 1) * 8;
    const int k_row = lane & 7;
    const int v_blk = lane >> 4;
    const int v_row = lane & 15;

    int cur = 0;
    for (int blk = 0; blk < NBLK; blk++) {
        // mask_b prefetch to regs (independent of the cp.async pipeline)
        float2 mk0[8], mk1[8];
        {
            const int s0g = blk * ABS;
#pragma unroll
            for (int nf = 0; nf < 8; nf++) {
                const int scol = s0g + nf * 8 + qr * 2;
                mk0[nf] = __ldg(reinterpret_cast<const float2*>(maskb + (size_t)tr0 * T_LEN + scol));
                mk1[nf] = __ldg(reinterpret_cast<const float2*>(maskb + (size_t)tr1 * T_LEN + scol));
            }
        }
        // wait for stage `cur`, ONE barrier, then refill stage (cur+2)%3
        if (blk + 1 < NBLK) cp_wait<1>(); else cp_wait<0>();
        __syncthreads();
        if (blk + 2 < NBLK) {
            load_kv_stage(blk + 2);
            cp_commit();
        }

        if (blk == 0) {
#pragma unroll
            for (int ks = 0; ks < 4; ks++) {
                uint32_t aoff = sw128((uint32_t)(wr0 + (lane & 15)) * 128 +
                                      (uint32_t)(ks * 16 + (lane >> 4) * 8) * 2);
                ldm_x4(qfh[ks], sb + AQ_H + aoff);
            }
        }

        const uint32_t B = sb + AST0 + (uint32_t)cur * AST_STRIDE;

        // ---- S2 = (Q*log2e) K ----
        float S[8][4];
#pragma unroll
        for (int i = 0; i < 8; i++)
#pragma unroll
            for (int q = 0; q < 4; q++) S[i][q] = 0.f;
#pragma unroll
        for (int ks = 0; ks < 4; ks++) {
#pragma unroll
            for (int nfp = 0; nfp < 4; nfp++) {
                uint32_t boff = sw128((uint32_t)((2 * nfp + k_nf_off) * 8 + k_row) * 128 +
                                      (uint32_t)(ks * 16 + k_k8) * 2);
                uint32_t kh[4];
                ldm_x4(kh, B + S_KH + boff);
                mma16816(S[2 * nfp + 0], qfh[ks], kh);
                mma16816(S[2 * nfp + 1], qfh[ks], kh + 2);
            }
        }

        // ---- S2 += (mask_b + bias)*log2e ; row max ----
        const float* bias_s = (const float*)(smc + AST0 + (size_t)cur * AST_STRIDE + S_BIAS);
        float rmax0 = -1e30f, rmax1 = -1e30f;
#pragma unroll
        for (int nf = 0; nf < 8; nf++) {
            const int sloc = nf * 8 + qr * 2;
            float2 ba = *reinterpret_cast<const float2*>(bias_s + (size_t)tl0 * BIAS_ST + sloc);
            float2 bb = *reinterpret_cast<const float2*>(bias_s + (size_t)(tl0 + 8) * BIAS_ST + sloc);
            S[nf][0] = fmaf(mk0[nf].x + ba.x, LOG2E, S[nf][0]);
            S[nf][1] = fmaf(mk0[nf].y + ba.y, LOG2E, S[nf][1]);
            S[nf][2] = fmaf(mk1[nf].x + bb.x, LOG2E, S[nf][2]);
            S[nf][3] = fmaf(mk1[nf].y + bb.y, LOG2E, S[nf][3]);
            rmax0 = fmaxf(rmax0, fmaxf(S[nf][0], S[nf][1]));
            rmax1 = fmaxf(rmax1, fmaxf(S[nf][2], S[nf][3]));
        }
        rmax0 = fmaxf(rmax0, __shfl_xor_sync(0xffffffffu, rmax0, 1));
        rmax0 = fmaxf(rmax0, __shfl_xor_sync(0xffffffffu, rmax0, 2));
        rmax1 = fmaxf(rmax1, __shfl_xor_sync(0xffffffffu, rmax1, 1));
        rmax1 = fmaxf(rmax1, __shfl_xor_sync(0xffffffffu, rmax1, 2));

        const float mn0 = fmaxf(m0, rmax0), mn1 = fmaxf(m1, rmax1);
        const float es0 = ex2f(m0 - mn0), es1 = ex2f(m1 - mn1);
        m0 = mn0; m1 = mn1;

        float rs0 = 0.f, rs1 = 0.f;
#pragma unroll
        for (int nf = 0; nf < 8; nf++) {
            S[nf][0] = ex2f(S[nf][0] - mn0);
            S[nf][1] = ex2f(S[nf][1] - mn0);
            S[nf][2] = ex2f(S[nf][2] - mn1);
            S[nf][3] = ex2f(S[nf][3] - mn1);
            rs0 += S[nf][0] + S[nf][1];
            rs1 += S[nf][2] + S[nf][3];
        }
        rs0 += __shfl_xor_sync(0xffffffffu, rs0, 1);
        rs0 += __shfl_xor_sync(0xffffffffu, rs0, 2);
        rs1 += __shfl_xor_sync(0xffffffffu, rs1, 1);
        rs1 += __shfl_xor_sync(0xffffffffu, rs1, 2);
        l0 = l0 * es0 + rs0;
        l1 = l1 * es1 + rs1;

#pragma unroll
        for (int i = 0; i < 8; i++) {
            O[i][0] *= es0; O[i][1] *= es0;
            O[i][2] *= es1; O[i][3] *= es1;
        }

        // ---- O += Ph Vh ----
#pragma unroll
        for (int kp = 0; kp < 4; kp++) {
            uint32_t ah[4];
            ah[0] = pack_hi2(S[2*kp][0],   S[2*kp][1]);
            ah[1] = pack_hi2(S[2*kp][2],   S[2*kp][3]);
            ah[2] = pack_hi2(S[2*kp+1][0], S[2*kp+1][1]);
            ah[3] = pack_hi2(S[2*kp+1][2], S[2*kp+1][3]);
#pragma unroll
            for (int np = 0; np < 4; np++) {
                uint32_t voff = sw128((uint32_t)(kp * 16 + v_row) * 128 +
                                      (uint32_t)(2 * np + v_blk) * 16);
                uint32_t vh[4];
                ldm_x4_trans(vh, B + S_VH + voff);
                mma16816(O[2 * np + 0], ah, vh);
                mma16816(O[2 * np + 1], ah, vh + 2);
            }
        }
        cur++; if (cur >= 3) cur -= 3;
    }

    // ---- normalize + write fp16 hi ----
    const float inv0 = 1.f / l0, inv1 = 1.f / l1;
    const size_t base0 = ((size_t)tr0 * BSZ + b) * EMBED + h * 64;
    const size_t base1 = ((size_t)tr1 * BSZ + b) * EMBED + h * 64;
#pragma unroll
    for (int nf2 = 0; nf2 < 8; nf2++) {
        const int d0 = nf2 * 8 + qr * 2;
        float v0 = O[nf2][0] * inv0, v1 = O[nf2][1] * inv0;
        float w0 = O[nf2][2] * inv1, w1 = O[nf2][3] * inv1;
        *reinterpret_cast<uint32_t*>(g_attnh + base0 + d0) = pack_hi2(v0, v1);
        *reinterpret_cast<uint32_t*>(g_attnh + base1 + d0) = pack_hi2(w0, w1);
    }
}

// ---------------------------------------------------------------------------
extern "C" void kernel_launch(void* const* d_in, const int* in_sizes, int n_in,
                              void* d_out, int out_size)
{
    const float* query     = (const float*)d_in[0];
    const int*   kpm       = (const int*)  d_in[1];
    const float* attn_mask = (const float*)d_in[2];
    const float* attn_bias = (const float*)d_in[3];
    const float* W_in      = (const float*)d_in[4];
    const float* b_in      = (const float*)d_in[5];
    const float* W_out     = (const float*)d_in[6];
    const float* b_out     = (const float*)d_in[7];
    float*       out       = (float*)d_out;

    static bool attr_set = false;
    if (!attr_set) {
        cudaFuncSetAttribute(gemm_mma, cudaFuncAttributeMaxDynamicSharedMemorySize, GEMM_SMEM);
        cudaFuncSetAttribute(attn_mma_kernel, cudaFuncAttributeMaxDynamicSharedMemorySize, ATTN_SMEM);
        attr_set = true;
    }

    __half *Ah, *Bh, *ATh;
    cudaGetSymbolAddress((void**)&Ah, g_Ah);
    cudaGetSymbolAddress((void**)&Bh, g_Bh);
    cudaGetSymbolAddress((void**)&ATh, g_attnh);

    // 1) prep: hi-only splits + mask fold
    split_hi_kernel<<<MROWS * EMBED / 4 / 256, 256>>>(query, Ah, MROWS * EMBED / 4);
    split_hi_kernel<<<3 * EMBED * EMBED / 4 / 256, 256>>>(W_in, Bh, 3 * EMBED * EMBED / 4);
    prep_mask_kernel<<<BSZ * T_LEN * T_LEN / 4 / 256, 256>>>(attn_mask, kpm);

    // 2) QKV projection -> fp16 q(scaled by 0.125*log2e)/k/v
    {
        dim3 grid(3 * EMBED / TN, MROWS / TM);   // (24, 32)
        gemm_mma<<<grid, 256, GEMM_SMEM>>>(Ah, Bh, b_in, 0, nullptr);
    }

    // 3) Flash attention -> fp16 attn (hi)
    {
        dim3 grid(T_LEN / ABT, NBH);   // (8, 64)
        attn_mma_kernel<<<grid, 256, ATTN_SMEM>>>(attn_bias);
    }

    // 4) split W_out (hi); output projection (A = attn fp16 hi)
    split_hi_kernel<<<EMBED * EMBED / 4 / 256, 256>>>(W_out, Bh, EMBED * EMBED / 4);
    {
        dim3 grid(EMBED / TN, MROWS / TM);       // (8, 32)
        gemm_mma<<<grid, 256, GEMM_SMEM>>>(ATh, Bh, b_out, 1, out);
    }
}